// round 15
// baseline (speedup 1.0000x reference)
#include <cuda_runtime.h>
#include <cuda_bf16.h>
#include <math.h>

#define Bb 2
#define Tt 2048
#define Cc 1024
#define Hh 16
#define Dd 64
#define MM (Bb*Tt)   // 4096 rows

// ---------------- scratch (device globals; no allocation allowed) ----------------
__device__ float g_y[3][(size_t)MM * Cc];          // q,k,v projections (dense)
__device__ float g_q [(size_t)Bb*Hh*Tt*Dd];        // sparsified q  [B,H,T,D]
__device__ float g_kT[(size_t)Bb*Hh*Dd*Tt];        // sparsified k^T [B,H,D,T]
__device__ float g_v [(size_t)Bb*Hh*Tt*Dd];        // sparsified v  [B,H,T,D]
__device__ float g_att[(size_t)MM * Cc];           // attention output [B,T,C]

// 2-term bf16 splits for the OUTPUT projection only (selection-insensitive):
__device__ __align__(256) __nv_bfloat16 g_a2[2][(size_t)MM * Cc];   // g_att splits
__device__ __align__(256) __nv_bfloat16 g_w2[2][(size_t)Cc * Cc];   // Wo splits

// order-preserving float -> uint mapping (monotonic increasing, no NaNs present)
__device__ __forceinline__ unsigned okey(float x){
    unsigned m = __float_as_uint(x);
    return (m & 0x80000000u) ? ~m : (m | 0x80000000u);
}

// ---- packed dual-fp32 ops (each half is an exact rn op: bit-identical to scalar) ----
typedef unsigned long long u64t;
__device__ __forceinline__ u64t pack2(float lo, float hi){
    u64t r; asm("mov.b64 %0, {%1, %2};" : "=l"(r) : "f"(lo), "f"(hi)); return r;
}
__device__ __forceinline__ void unpack2(float& lo, float& hi, u64t v){
    asm("mov.b64 {%0, %1}, %2;" : "=f"(lo), "=f"(hi) : "l"(v));
}
__device__ __forceinline__ u64t fma2(u64t a, u64t b, u64t c){
    u64t r; asm("fma.rn.f32x2 %0, %1, %2, %3;" : "=l"(r) : "l"(a), "l"(b), "l"(c)); return r;
}
__device__ __forceinline__ u64t add2(u64t a, u64t b){
    u64t r; asm("add.rn.f32x2 %0, %1, %2;" : "=l"(r) : "l"(a), "l"(b)); return r;
}

// ---------------- PTX helpers (mma.sync / ldmatrix / cp.async; baseline sm_80+) ----
__device__ __forceinline__ void ldsm4(unsigned& r0, unsigned& r1, unsigned& r2, unsigned& r3, unsigned addr){
    asm volatile("ldmatrix.sync.aligned.m8n8.x4.shared.b16 {%0,%1,%2,%3}, [%4];"
        : "=r"(r0), "=r"(r1), "=r"(r2), "=r"(r3) : "r"(addr));
}
__device__ __forceinline__ void mma16816(float* c, const unsigned* a, const unsigned* b){
    asm volatile("mma.sync.aligned.m16n8k16.row.col.f32.bf16.bf16.f32 "
        "{%0,%1,%2,%3}, {%4,%5,%6,%7}, {%8,%9}, {%0,%1,%2,%3};"
        : "+f"(c[0]), "+f"(c[1]), "+f"(c[2]), "+f"(c[3])
        : "r"(a[0]), "r"(a[1]), "r"(a[2]), "r"(a[3]), "r"(b[0]), "r"(b[1]));
}
__device__ __forceinline__ void cpa16(unsigned dst, const void* src){
    asm volatile("cp.async.cg.shared.global [%0], [%1], 16;" :: "r"(dst), "l"(src));
}
__device__ __forceinline__ void cpa_commit(){
    asm volatile("cp.async.commit_group;" ::: "memory");
}
template<int N>
__device__ __forceinline__ void cpa_wait(){
    asm volatile("cp.async.wait_group %0;" :: "n"(N) : "memory");
}

// warp-dedup'd histogram add (exact counting; fewer atomic instructions)
__device__ __forceinline__ void hadd(unsigned* hist, unsigned bin){
    unsigned am = __activemask();
    unsigned mk = __match_any_sync(am, bin);
    if ((__ffs(mk) - 1) == (threadIdx.x & 31))
        atomicAdd(&hist[bin], (unsigned)__popc(mk));
}

// ------ 128x64 fp32 GEMM tile (K-chunk 32 = 2 sequential 16-k groups; per-element
// FMA order IDENTICAL to the round-7/12/13 kernel -> bit-identical results) ------
__device__ __forceinline__ void sgemm_tile(
    const float* __restrict__ A, const float* __restrict__ Bw,
    float* __restrict__ Cmat, int K, int N, int mTile, int nTile)
{
    __shared__ __align__(16) float As[32][128];
    __shared__ __align__(16) float Bs[32][64];
    const int tid = threadIdx.x;
    const int ldm  = tid >> 1;
    const int ldk  = (tid & 1) << 3;
    const int ldbm = tid >> 2;
    const int ldbk = (tid & 3) << 2;
    const int ry  = tid >> 4;
    const int rx  = tid & 15;
    const int m0 = mTile * 128, n0 = nTile * 64;

    u64t acc2[4][4];
    #pragma unroll
    for (int i = 0; i < 4; ++i)
        #pragma unroll
        for (int j = 0; j < 4; ++j) acc2[i][j] = 0ull;

    const float* Aptr = A  + (size_t)(m0 + ldm)  * K + ldk;
    const float* Bptr = Bw + (size_t)(n0 + ldbm) * K + ldbk;

    for (int k0 = 0; k0 < K; k0 += 32) {
        #pragma unroll
        for (int hlf = 0; hlf < 2; ++hlf){
            float4 a0 = *(const float4*)(Aptr + k0 + hlf*16);
            float4 a1 = *(const float4*)(Aptr + k0 + hlf*16 + 4);
            float4 b0 = *(const float4*)(Bptr + k0 + hlf*16);
            const int kb = hlf*16;
            As[kb+ldk+0][ldm]=a0.x; As[kb+ldk+1][ldm]=a0.y; As[kb+ldk+2][ldm]=a0.z; As[kb+ldk+3][ldm]=a0.w;
            As[kb+ldk+4][ldm]=a1.x; As[kb+ldk+5][ldm]=a1.y; As[kb+ldk+6][ldm]=a1.z; As[kb+ldk+7][ldm]=a1.w;
            Bs[kb+ldbk+0][ldbm]=b0.x; Bs[kb+ldbk+1][ldbm]=b0.y; Bs[kb+ldbk+2][ldbm]=b0.z; Bs[kb+ldbk+3][ldbm]=b0.w;
        }
        __syncthreads();

        #pragma unroll
        for (int hlf = 0; hlf < 2; ++hlf){
            u64t tacc2[4][4];
            #pragma unroll
            for (int i = 0; i < 4; ++i)
                #pragma unroll
                for (int j = 0; j < 4; ++j) tacc2[i][j] = 0ull;

            #pragma unroll
            for (int kk = 0; kk < 16; ++kk) {
                const u64t* a2 = (const u64t*)&As[hlf*16 + kk][ry<<3];
                float4 bf0 = *(const float4*)&Bs[hlf*16 + kk][rx<<2];
                u64t av[4] = {a2[0], a2[1], a2[2], a2[3]};
                u64t bvv[4] = {pack2(bf0.x,bf0.x), pack2(bf0.y,bf0.y),
                               pack2(bf0.z,bf0.z), pack2(bf0.w,bf0.w)};
                #pragma unroll
                for (int i = 0; i < 4; ++i)
                    #pragma unroll
                    for (int j = 0; j < 4; ++j)
                        tacc2[i][j] = fma2(av[i], bvv[j], tacc2[i][j]);
            }
            #pragma unroll
            for (int i = 0; i < 4; ++i)
                #pragma unroll
                for (int j = 0; j < 4; ++j) acc2[i][j] = add2(acc2[i][j], tacc2[i][j]);
        }
        __syncthreads();
    }
    #pragma unroll
    for (int i = 0; i < 4; ++i){
        float lo[4], hi[4];
        #pragma unroll
        for (int j = 0; j < 4; ++j) unpack2(lo[j], hi[j], acc2[i][j]);
        int row = m0 + (ry<<3) + 2*i;
        float4 c0 = {lo[0], lo[1], lo[2], lo[3]};
        float4 c1 = {hi[0], hi[1], hi[2], hi[3]};
        *(float4*)&Cmat[(size_t)row*N + n0 + (rx<<2)]       = c0;
        *(float4*)&Cmat[(size_t)(row+1)*N + n0 + (rx<<2)]   = c1;
    }
}

extern "C" __global__ void __launch_bounds__(256, 2)
k_qkv(const float* __restrict__ x, const float* __restrict__ Wq,
      const float* __restrict__ Wk, const float* __restrict__ Wv)
{
    const float* W = (blockIdx.z == 0) ? Wq : (blockIdx.z == 1) ? Wk : Wv;
    sgemm_tile(x, W, g_y[blockIdx.z], Cc, Cc, blockIdx.y, blockIdx.x);
}

// ---------------- 2-term bf16 split (output projection operands only) ----------------
extern "C" __global__ void __launch_bounds__(256)
k_split2(const float* __restrict__ src, int which, int n)
{
    int i = blockIdx.x * 256 + threadIdx.x;
    if (i * 4 >= n) return;
    const float* s = which ? src : (const float*)g_att;
    __nv_bfloat16* d1 = which ? g_w2[0] : g_a2[0];
    __nv_bfloat16* d2 = which ? g_w2[1] : g_a2[1];

    float4 v = *(const float4*)(s + (size_t)i*4);
    float x4[4] = {v.x, v.y, v.z, v.w};
    unsigned short u1[4], u2[4];
    #pragma unroll
    for (int j = 0; j < 4; ++j){
        float x = x4[j];
        __nv_bfloat16 b1 = __float2bfloat16_rn(x);
        float r = x - __bfloat162float(b1);
        __nv_bfloat16 b2 = __float2bfloat16_rn(r);
        u1[j] = *(unsigned short*)&b1;
        u2[j] = *(unsigned short*)&b2;
    }
    *(uint2*)((char*)d1 + (size_t)i*8) = make_uint2(u1[0] | ((unsigned)u1[1]<<16), u1[2] | ((unsigned)u1[3]<<16));
    *(uint2*)((char*)d2 + (size_t)i*8) = make_uint2(u2[0] | ((unsigned)u2[1]<<16), u2[2] | ((unsigned)u2[3]<<16));
}

// ------ emulated-fp32 OUT GEMM via mma.sync bf16 (CTA 128x64, K=1024, 2-term) ------
extern "C" __global__ void __launch_bounds__(256)
k_mma_out(float* __restrict__ out)
{
    __shared__ __align__(16) __nv_bfloat16 sm[2][4][128][16];   // 32KB
    const int tid = threadIdx.x, wid = tid >> 5, lane = tid & 31;
    const int warpM = wid & 3, warpN = wid >> 2;
    const int m0 = blockIdx.y * 128, n0 = blockIdx.x * 64;
    const __nv_bfloat16* segA[2] = {g_a2[0], g_a2[1]};
    const __nv_bfloat16* segB[2] = {g_w2[0], g_w2[1]};
    const int srow = tid >> 1, shalf = (tid & 1) << 3;
    const unsigned smbase = (unsigned)__cvta_generic_to_shared(&sm[0][0][0][0]);

    float accH[2][4][4], accL[2][4][4];
    #pragma unroll
    for (int mt = 0; mt < 2; ++mt)
        #pragma unroll
        for (int nf = 0; nf < 4; ++nf)
            #pragma unroll
            for (int r = 0; r < 4; ++r){ accH[mt][nf][r] = 0.f; accL[mt][nf][r] = 0.f; }

    #pragma unroll
    for (int s = 0; s < 2; ++s)
        cpa16(smbase + (unsigned)(((s*128 + srow)*16 + shalf)*2),
              segA[s] + (size_t)(m0 + srow)*Cc + shalf);
    if (tid < 128){
        #pragma unroll
        for (int s = 0; s < 2; ++s)
            cpa16(smbase + (unsigned)((((2+s)*128 + srow)*16 + shalf)*2),
                  segB[s] + (size_t)(n0 + srow)*Cc + shalf);
    }
    cpa_commit();

    for (int ch = 0; ch < 64; ++ch){
        const int buf = ch & 1;
        if (ch < 63){
            const unsigned bofs = (unsigned)((buf^1)*4*128*16*2);
            #pragma unroll
            for (int s = 0; s < 2; ++s)
                cpa16(smbase + bofs + (unsigned)(((s*128 + srow)*16 + shalf)*2),
                      segA[s] + (size_t)(m0 + srow)*Cc + (ch+1)*16 + shalf);
            if (tid < 128){
                #pragma unroll
                for (int s = 0; s < 2; ++s)
                    cpa16(smbase + bofs + (unsigned)((((2+s)*128 + srow)*16 + shalf)*2),
                          segB[s] + (size_t)(n0 + srow)*Cc + (ch+1)*16 + shalf);
            }
            cpa_commit();
            cpa_wait<1>();
        } else {
            cpa_wait<0>();
        }
        __syncthreads();

        unsigned af[2][2][4];
        #pragma unroll
        for (int s = 0; s < 2; ++s)
            #pragma unroll
            for (int mt = 0; mt < 2; ++mt){
                int row = warpM*32 + mt*16 + (lane & 15);
                unsigned ad = smbase + (unsigned)((((buf*4 + s)*128 + row)*16 + ((lane>>4)<<3))*2);
                ldsm4(af[s][mt][0], af[s][mt][1], af[s][mt][2], af[s][mt][3], ad);
            }
        #pragma unroll
        for (int n2 = 0; n2 < 2; ++n2){
            unsigned bfr[2][4];
            #pragma unroll
            for (int s = 0; s < 2; ++s){
                int row = warpN*32 + n2*16 + ((lane>>4)<<3) + (lane & 7);
                unsigned bd = smbase + (unsigned)((((buf*4 + 2 + s)*128 + row)*16 + (((lane>>3)&1)<<3))*2);
                ldsm4(bfr[s][0], bfr[s][1], bfr[s][2], bfr[s][3], bd);
            }
            #pragma unroll
            for (int mt = 0; mt < 2; ++mt)
                #pragma unroll
                for (int nt = 0; nt < 2; ++nt){
                    mma16816(accH[mt][n2*2+nt], af[0][mt], &bfr[0][nt*2]);
                    mma16816(accL[mt][n2*2+nt], af[0][mt], &bfr[1][nt*2]);
                    mma16816(accL[mt][n2*2+nt], af[1][mt], &bfr[0][nt*2]);
                }
        }
        __syncthreads();
    }

    const int g = lane >> 2, t4 = lane & 3;
    #pragma unroll
    for (int mt = 0; mt < 2; ++mt){
        int r0 = m0 + warpM*32 + mt*16 + g;
        #pragma unroll
        for (int nf = 0; nf < 4; ++nf){
            int col = n0 + warpN*32 + nf*8 + 2*t4;
            *(float2*)&out[(size_t)r0*Cc + col]     = make_float2(accH[mt][nf][0] + accL[mt][nf][0],
                                                                 accH[mt][nf][1] + accL[mt][nf][1]);
            *(float2*)&out[(size_t)(r0+8)*Cc + col] = make_float2(accH[mt][nf][2] + accL[mt][nf][2],
                                                                 accH[mt][nf][3] + accL[mt][nf][3]);
        }
    }
}

// ---------------- feature-dim top-8 sparsify (+ layout transforms) ----------------
extern "C" __global__ void __launch_bounds__(256)
k_sparsify()
{
    const int z   = blockIdx.y;                    // 0=q, 1=k, 2=v
    const int idx = blockIdx.x * 256 + threadIdx.x; // over B*T*H = 65536
    const int t = idx & (Tt - 1);
    const int h = (idx >> 11) & (Hh - 1);
    const int b = idx >> 15;

    const float* src = g_y[z] + ((size_t)(b*Tt + t))*Cc + h*Dd;
    float v[64];
    #pragma unroll
    for (int i = 0; i < 16; ++i){
        float4 f = *(const float4*)(src + i*4);
        v[4*i] = f.x; v[4*i+1] = f.y; v[4*i+2] = f.z; v[4*i+3] = f.w;
    }
    float thr[8];
    #pragma unroll
    for (int i = 0; i < 8; ++i) thr[i] = -1.f;
    #pragma unroll
    for (int d2 = 0; d2 < 64; ++d2){
        float a = fabsf(v[d2]);
        if (a > thr[0]){
            thr[0] = a;
            #pragma unroll
            for (int p = 0; p < 7; ++p){
                if (thr[p] > thr[p+1]){ float tmp = thr[p]; thr[p] = thr[p+1]; thr[p+1] = tmp; }
            }
        }
    }
    const float kth = thr[0];
    const size_t bh = (size_t)b*Hh + h;
    if (z == 1){
        #pragma unroll
        for (int d2 = 0; d2 < 64; ++d2){
            float val = (fabsf(v[d2]) >= kth) ? v[d2] : 0.f;
            g_kT[(bh*Dd + d2)*Tt + t] = val;     // coalesced over t within warp
        }
    } else {
        float* dst = ((z == 0) ? g_q : g_v) + (bh*Tt + t)*Dd;
        #pragma unroll
        for (int i = 0; i < 16; ++i){
            float4 o;
            o.x = (fabsf(v[4*i  ]) >= kth) ? v[4*i  ] : 0.f;
            o.y = (fabsf(v[4*i+1]) >= kth) ? v[4*i+1] : 0.f;
            o.z = (fabsf(v[4*i+2]) >= kth) ? v[4*i+2] : 0.f;
            o.w = (fabsf(v[4*i+3]) >= kth) ? v[4*i+3] : 0.f;
            *(float4*)(dst + 4*i) = o;
        }
    }
}

// ---- radix-select: find bin of rank-th largest. Warp-shuffle suffix scan, 2 barriers ----
__device__ __forceinline__ void radix_find(const unsigned* hist, int* scr,
                                           int rank, int tid, int* s_io)
{
    const int lane = tid & 31, wrp = tid >> 5;
    int sum = 0;
    #pragma unroll
    for (int i = 0; i < 8; ++i) sum += (int)hist[(tid<<3) + i];
    int v = sum;
    #pragma unroll
    for (int off = 1; off < 32; off <<= 1){
        int o = __shfl_down_sync(0xFFFFFFFFu, v, off);
        if (lane + off < 32) v += o;
    }
    if (lane == 0) scr[wrp] = v;    // warp total
    __syncthreads();
    int wsuf = 0;
    #pragma unroll
    for (int w = 0; w < 8; ++w) if (w > wrp) wsuf += scr[w];
    const int suff = v + wsuf;
    const int suffNext = suff - sum;
    if (suff >= rank && suffNext < rank){   // exactly one thread
        int c = suffNext;
        int bin = tid << 3;
        for (int i = (tid<<3) + 7; i >= (tid<<3); --i){
            if (c + (int)hist[i] >= rank){ bin = i; break; }
            c += (int)hist[i];
        }
        s_io[0] = bin; s_io[1] = rank - c;
    }
    __syncthreads();
}

// ---------------- fused sparse attention: one block per (b,h,t) query row ----------------
extern "C" __global__ void __launch_bounds__(256)
k_attn()
{
    __shared__ __align__(16) float s_scores[2048];
    __shared__ __align__(16) unsigned s_hist[2048];
    __shared__ __align__(16) unsigned short s_sel[2048];
    __shared__ float s_red[256];
    __shared__ float s_wred[8];
    __shared__ float s_qval[64];
    __shared__ int   s_qidx[64];
    __shared__ int   s_wcnt[8];
    __shared__ int   s_io[2];
    __shared__ int   s_nq;

    const int tid = threadIdx.x;
    const int lane = tid & 31, wrp = tid >> 5;
    const int t = Tt - 1 - (int)blockIdx.x;   // heavy rows first
    const int h = blockIdx.y, b = blockIdx.z;
    const int len = t + 1;
    const size_t bh = (size_t)b*Hh + h;
    const bool selAll = (len <= 256);

    // ---- clear hist (only needed when radix select will run) + load q row ----
    if (!selAll){
        #pragma unroll
        for (int i = 0; i < 8; ++i) s_hist[tid + (i<<8)] = 0;
    }
    if (tid < 64) s_red[tid] = g_q[(bh*Tt + t)*Dd + tid];
    __syncthreads();
    if (tid == 0){
        int n = 0;
        for (int d = 0; d < 64; ++d){
            float qv = s_red[d];
            if (qv != 0.f){ s_qidx[n] = d; s_qval[n] = qv; ++n; }
        }
        s_nq = n;
    }
    __syncthreads();
    const int nq = s_nq;

    // ---- scores (sparse-q AXPY, ascending d) fused with pass-0 hist + row max ----
    const float* __restrict__ kT = g_kT + bh*Dd*Tt;
    float mloc = -__int_as_float(0x7F800000);   // -inf
    for (int s0 = tid*4; s0 < len; s0 += 1024){
        float ax=0.f, ay=0.f, az=0.f, aw=0.f;
        #pragma unroll 8
        for (int j = 0; j < nq; ++j){
            float qv = s_qval[j];
            float4 kv = *(const float4*)(kT + (size_t)s_qidx[j]*Tt + s0);
            ax = fmaf(qv, kv.x, ax); ay = fmaf(qv, kv.y, ay);
            az = fmaf(qv, kv.z, az); aw = fmaf(qv, kv.w, aw);
        }
        float4 r = {ax*0.125f, ay*0.125f, az*0.125f, aw*0.125f};
        *(float4*)(s_scores + s0) = r;
        const int rem = len - s0;   // >= 1
        if (rem >= 4){
            mloc = fmaxf(fmaxf(fmaxf(fmaxf(mloc, r.x), r.y), r.z), r.w);
            if (!selAll){
                hadd(s_hist, okey(r.x) >> 21);
                hadd(s_hist, okey(r.y) >> 21);
                hadd(s_hist, okey(r.z) >> 21);
                hadd(s_hist, okey(r.w) >> 21);
            }
        } else {
            float vv[4] = {r.x, r.y, r.z, r.w};
            for (int e = 0; e < rem; ++e){
                mloc = fmaxf(mloc, vv[e]);
                if (!selAll) atomicAdd(&s_hist[okey(vv[e]) >> 21], 1u);
            }
        }
    }
    #pragma unroll
    for (int off = 16; off; off >>= 1)
        mloc = fmaxf(mloc, __shfl_xor_sync(0xFFFFFFFFu, mloc, off));
    if (lane == 0) s_wred[wrp] = mloc;
    __syncthreads();
    float m = s_wred[0];
    #pragma unroll
    for (int w = 1; w < 8; ++w) m = fmaxf(m, s_wred[w]);

    // ---- exact 256th-largest threshold via 3-pass radix select (float4 scans) ----
    unsigned thresh_u = 0;
    if (!selAll){
        int rank = 256;
        radix_find(s_hist, (int*)s_red, rank, tid, s_io);
        const unsigned b0 = (unsigned)s_io[0]; rank = s_io[1];
        __syncthreads();
        #pragma unroll
        for (int i = 0; i < 8; ++i) s_hist[tid + (i<<8)] = 0;
        __syncthreads();
        for (int s4 = tid*4; s4 < len; s4 += 1024){
            float4 sc = *(const float4*)(s_scores + s4);
            const int rem = len - s4;
            unsigned u;
            u = okey(sc.x); if ((u >> 21) == b0) atomicAdd(&s_hist[(u >> 10) & 0x7FFu], 1u);
            if (rem > 1){ u = okey(sc.y); if ((u >> 21) == b0) atomicAdd(&s_hist[(u >> 10) & 0x7FFu], 1u); }
            if (rem > 2){ u = okey(sc.z); if ((u >> 21) == b0) atomicAdd(&s_hist[(u >> 10) & 0x7FFu], 1u); }
            if (rem > 3){ u = okey(sc.w); if ((u >> 21) == b0) atomicAdd(&s_hist[(u >> 10) & 0x7FFu], 1u); }
        }
        __syncthreads();
        radix_find(s_hist, (int*)s_red, rank, tid, s_io);
        const unsigned b1 = (unsigned)s_io[0]; rank = s_io[1];
        __syncthreads();
        #pragma unroll
        for (int i = 0; i < 8; ++i) s_hist[tid + (i<<8)] = 0;
        __syncthreads();
        const unsigned hi21 = (b0 << 11) | b1;
        for (int s4 = tid*4; s4 < len; s4 += 1024){
            float4 sc = *(const float4*)(s_scores + s4);
            const int rem = len - s4;
            unsigned u;
            u = okey(sc.x); if ((u >> 10) == hi21) atomicAdd(&s_hist[u & 0x3FFu], 1u);
            if (rem > 1){ u = okey(sc.y); if ((u >> 10) == hi21) atomicAdd(&s_hist[u & 0x3FFu], 1u); }
            if (rem > 2){ u = okey(sc.z); if ((u >> 10) == hi21) atomicAdd(&s_hist[u & 0x3FFu], 1u); }
            if (rem > 3){ u = okey(sc.w); if ((u >> 10) == hi21) atomicAdd(&s_hist[u & 0x3FFu], 1u); }
        }
        __syncthreads();
        radix_find(s_hist, (int*)s_red, rank, tid, s_io);
        const unsigned b2 = (unsigned)s_io[0];
        __syncthreads();
        thresh_u = (b0 << 21) | (b1 << 10) | b2;
    }

    // ---- ordered compaction FUSED with softmax-weight generation ----
    // (e = exp(score - m) written at compaction position; Z accumulated locally.
    //  Z order change is post-selection -> ~1e-7 uniform effect only.)
    float* s_wf = (float*)s_hist;   // hist no longer needed
    float zp = 0.f;
    int base = 0;
    for (int c0 = 0; c0 < len; c0 += 1024){
        const int s4 = c0 + tid*4;
        unsigned pb = 0; int cnt = 0;
        float4 sc = make_float4(0.f, 0.f, 0.f, 0.f);
        if (s4 < len){
            sc = *(const float4*)(s_scores + s4);
            const int rem = len - s4;
            if (selAll || okey(sc.x) >= thresh_u){ pb |= 1u; ++cnt; }
            if (rem > 1 && (selAll || okey(sc.y) >= thresh_u)){ pb |= 2u; ++cnt; }
            if (rem > 2 && (selAll || okey(sc.z) >= thresh_u)){ pb |= 4u; ++cnt; }
            if (rem > 3 && (selAll || okey(sc.w) >= thresh_u)){ pb |= 8u; ++cnt; }
        }
        int incl = cnt;
        #pragma unroll
        for (int off = 1; off < 32; off <<= 1){
            int o = __shfl_up_sync(0xFFFFFFFFu, incl, off);
            if (lane >= off) incl += o;
        }
        if (lane == 31) s_wcnt[wrp] = incl;
        __syncthreads();
        int woff = base, tot = 0;
        #pragma unroll
        for (int w = 0; w < 8; ++w){ int cg = s_wcnt[w]; if (w < wrp) woff += cg; tot += cg; }
        int pos = woff + (incl - cnt);
        const float scv[4] = {sc.x, sc.y, sc.z, sc.w};
        #pragma unroll
        for (int e = 0; e < 4; ++e){
            if ((pb >> e) & 1u){
                float ev = __expf(scv[e] - m);
                s_sel[pos] = (unsigned short)(s4 + e);
                s_wf[pos]  = ev;
                zp += ev;
                ++pos;
            }
        }
        base += tot;
        __syncthreads();
    }
    const int nsel = base;

    // ---- Z reduction ----
    #pragma unroll
    for (int off = 16; off; off >>= 1)
        zp += __shfl_xor_sync(0xFFFFFFFFu, zp, off);
    if (lane == 0) s_wred[wrp] = zp;
    __syncthreads();
    float Z = 0.f;
    #pragma unroll
    for (int w = 0; w < 8; ++w) Z += s_wred[w];
    const float invZ = 1.0f / Z;

    // ---- out[d] = (sum of e * v[s,d]) * invZ  (blocked quads: vector LDS, MLP=4) ----
    const float* __restrict__ vp = g_v + bh*Tt*Dd;
    const int grp = tid >> 6, d = tid & 63;
    float a0 = 0.f, a1 = 0.f, a2 = 0.f, a3 = 0.f;
    const int nq4 = nsel >> 2;
    for (int q = grp; q < nq4; q += 4){
        const int c = q << 2;
        ushort4 e4 = *(const ushort4*)&s_sel[c];
        float4  w4 = *(const float4*)&s_wf[c];
        const float v0 = __ldg(vp + (size_t)e4.x*Dd + d);
        const float v1 = __ldg(vp + (size_t)e4.y*Dd + d);
        const float v2 = __ldg(vp + (size_t)e4.z*Dd + d);
        const float v3 = __ldg(vp + (size_t)e4.w*Dd + d);
        a0 = fmaf(w4.x, v0, a0); a1 = fmaf(w4.y, v1, a1);
        a2 = fmaf(w4.z, v2, a2); a3 = fmaf(w4.w, v3, a3);
    }
    for (int i = (nq4 << 2) + grp; i < nsel; i += 4)
        a0 = fmaf(s_wf[i], __ldg(vp + (size_t)s_sel[i]*Dd + d), a0);
    float acc = ((a0 + a1) + (a2 + a3)) * invZ;
    __syncthreads();   // s_red free for reuse
    s_red[tid] = acc;
    __syncthreads();
    if (grp == 0){
        float r = ((s_red[d] + s_red[64 + d]) + s_red[128 + d]) + s_red[192 + d];
        g_att[(((size_t)b*Tt + t)*Hh + h)*Dd + d] = r;
    }
}

// ---------------- launch ----------------
extern "C" void kernel_launch(void* const* d_in, const int* in_sizes, int n_in,
                              void* d_out, int out_size)
{
    (void)in_sizes; (void)n_in; (void)out_size;
    const float* x  = (const float*)d_in[0];
    const float* Wq = (const float*)d_in[1];
    const float* Wk = (const float*)d_in[2];
    const float* Wv = (const float*)d_in[3];
    const float* Wo = (const float*)d_in[4];
    float* out = (float*)d_out;

    const int nx = MM * Cc;      // 4M
    const int nw = Cc * Cc;      // 1M
    k_split2<<<nw/1024, 256>>>(Wo, 1, nw);           // Wo splits
    k_qkv<<<dim3(Cc/64, MM/128, 3), 256>>>(x, Wq, Wk, Wv);
    k_sparsify<<<dim3((Bb*Tt*Hh)/256, 3), 256>>>();
    k_attn<<<dim3(Tt, Hh, Bb), 256>>>();
    k_split2<<<nx/1024, 256>>>(x, 0, nx);            // g_att splits (src arg unused)
    k_mma_out<<<dim3(Cc/64, MM/128), 256>>>(out);
}

// round 16
// speedup vs baseline: 1.0518x; 1.0518x over previous
#include <cuda_runtime.h>
#include <cuda_bf16.h>
#include <math.h>

#define Bb 2
#define Tt 2048
#define Cc 1024
#define Hh 16
#define Dd 64
#define MM (Bb*Tt)   // 4096 rows

// ---------------- scratch (device globals; no allocation allowed) ----------------
__device__ float g_y[3][(size_t)MM * Cc];          // q,k,v projections (dense)
__device__ float g_q [(size_t)Bb*Hh*Tt*Dd];        // sparsified q  [B,H,T,D]
__device__ float g_kT[(size_t)Bb*Hh*Dd*Tt];        // sparsified k^T [B,H,D,T]
__device__ float g_v [(size_t)Bb*Hh*Tt*Dd];        // sparsified v  [B,H,T,D]
__device__ float g_att[(size_t)MM * Cc];           // attention output [B,T,C]

// 2-term bf16 splits for the OUTPUT projection only (selection-insensitive):
__device__ __align__(256) __nv_bfloat16 g_a2[2][(size_t)MM * Cc];   // g_att splits
__device__ __align__(256) __nv_bfloat16 g_w2[2][(size_t)Cc * Cc];   // Wo splits

// order-preserving float -> uint mapping (monotonic increasing, no NaNs present)
__device__ __forceinline__ unsigned okey(float x){
    unsigned m = __float_as_uint(x);
    return (m & 0x80000000u) ? ~m : (m | 0x80000000u);
}

// ---- packed dual-fp32 ops (each half is an exact rn op: bit-identical to scalar) ----
typedef unsigned long long u64t;
__device__ __forceinline__ u64t pack2(float lo, float hi){
    u64t r; asm("mov.b64 %0, {%1, %2};" : "=l"(r) : "f"(lo), "f"(hi)); return r;
}
__device__ __forceinline__ void unpack2(float& lo, float& hi, u64t v){
    asm("mov.b64 {%0, %1}, %2;" : "=f"(lo), "=f"(hi) : "l"(v));
}
__device__ __forceinline__ u64t fma2(u64t a, u64t b, u64t c){
    u64t r; asm("fma.rn.f32x2 %0, %1, %2, %3;" : "=l"(r) : "l"(a), "l"(b), "l"(c)); return r;
}
__device__ __forceinline__ u64t add2(u64t a, u64t b){
    u64t r; asm("add.rn.f32x2 %0, %1, %2;" : "=l"(r) : "l"(a), "l"(b)); return r;
}

// ---------------- PTX helpers (mma.sync / ldmatrix / cp.async; baseline sm_80+) ----
__device__ __forceinline__ void ldsm4(unsigned& r0, unsigned& r1, unsigned& r2, unsigned& r3, unsigned addr){
    asm volatile("ldmatrix.sync.aligned.m8n8.x4.shared.b16 {%0,%1,%2,%3}, [%4];"
        : "=r"(r0), "=r"(r1), "=r"(r2), "=r"(r3) : "r"(addr));
}
__device__ __forceinline__ void mma16816(float* c, const unsigned* a, const unsigned* b){
    asm volatile("mma.sync.aligned.m16n8k16.row.col.f32.bf16.bf16.f32 "
        "{%0,%1,%2,%3}, {%4,%5,%6,%7}, {%8,%9}, {%0,%1,%2,%3};"
        : "+f"(c[0]), "+f"(c[1]), "+f"(c[2]), "+f"(c[3])
        : "r"(a[0]), "r"(a[1]), "r"(a[2]), "r"(a[3]), "r"(b[0]), "r"(b[1]));
}
__device__ __forceinline__ void cpa16(unsigned dst, const void* src){
    asm volatile("cp.async.cg.shared.global [%0], [%1], 16;" :: "r"(dst), "l"(src));
}
__device__ __forceinline__ void cpa_commit(){
    asm volatile("cp.async.commit_group;" ::: "memory");
}
template<int N>
__device__ __forceinline__ void cpa_wait(){
    asm volatile("cp.async.wait_group %0;" :: "n"(N) : "memory");
}

// warp-dedup'd histogram add (exact counting; fewer atomic instructions)
__device__ __forceinline__ void hadd(unsigned* hist, unsigned bin){
    unsigned am = __activemask();
    unsigned mk = __match_any_sync(am, bin);
    if ((__ffs(mk) - 1) == (threadIdx.x & 31))
        atomicAdd(&hist[bin], (unsigned)__popc(mk));
}

// ------ 128x64 fp32 GEMM tile (K-chunk 32 = 2 sequential 16-k groups; per-element
// FMA order IDENTICAL to the round-7/12/13 kernel -> bit-identical results) ------
__device__ __forceinline__ void sgemm_tile(
    const float* __restrict__ A, const float* __restrict__ Bw,
    float* __restrict__ Cmat, int K, int N, int mTile, int nTile)
{
    __shared__ __align__(16) float As[32][128];
    __shared__ __align__(16) float Bs[32][64];
    const int tid = threadIdx.x;
    const int ldm  = tid >> 1;
    const int ldk  = (tid & 1) << 3;
    const int ldbm = tid >> 2;
    const int ldbk = (tid & 3) << 2;
    const int ry  = tid >> 4;
    const int rx  = tid & 15;
    const int m0 = mTile * 128, n0 = nTile * 64;

    u64t acc2[4][4];
    #pragma unroll
    for (int i = 0; i < 4; ++i)
        #pragma unroll
        for (int j = 0; j < 4; ++j) acc2[i][j] = 0ull;

    const float* Aptr = A  + (size_t)(m0 + ldm)  * K + ldk;
    const float* Bptr = Bw + (size_t)(n0 + ldbm) * K + ldbk;

    for (int k0 = 0; k0 < K; k0 += 32) {
        #pragma unroll
        for (int hlf = 0; hlf < 2; ++hlf){
            float4 a0 = *(const float4*)(Aptr + k0 + hlf*16);
            float4 a1 = *(const float4*)(Aptr + k0 + hlf*16 + 4);
            float4 b0 = *(const float4*)(Bptr + k0 + hlf*16);
            const int kb = hlf*16;
            As[kb+ldk+0][ldm]=a0.x; As[kb+ldk+1][ldm]=a0.y; As[kb+ldk+2][ldm]=a0.z; As[kb+ldk+3][ldm]=a0.w;
            As[kb+ldk+4][ldm]=a1.x; As[kb+ldk+5][ldm]=a1.y; As[kb+ldk+6][ldm]=a1.z; As[kb+ldk+7][ldm]=a1.w;
            Bs[kb+ldbk+0][ldbm]=b0.x; Bs[kb+ldbk+1][ldbm]=b0.y; Bs[kb+ldbk+2][ldbm]=b0.z; Bs[kb+ldbk+3][ldbm]=b0.w;
        }
        __syncthreads();

        #pragma unroll
        for (int hlf = 0; hlf < 2; ++hlf){
            u64t tacc2[4][4];
            #pragma unroll
            for (int i = 0; i < 4; ++i)
                #pragma unroll
                for (int j = 0; j < 4; ++j) tacc2[i][j] = 0ull;

            #pragma unroll
            for (int kk = 0; kk < 16; ++kk) {
                const u64t* a2 = (const u64t*)&As[hlf*16 + kk][ry<<3];
                float4 bf0 = *(const float4*)&Bs[hlf*16 + kk][rx<<2];
                u64t av[4] = {a2[0], a2[1], a2[2], a2[3]};
                u64t bvv[4] = {pack2(bf0.x,bf0.x), pack2(bf0.y,bf0.y),
                               pack2(bf0.z,bf0.z), pack2(bf0.w,bf0.w)};
                #pragma unroll
                for (int i = 0; i < 4; ++i)
                    #pragma unroll
                    for (int j = 0; j < 4; ++j)
                        tacc2[i][j] = fma2(av[i], bvv[j], tacc2[i][j]);
            }
            #pragma unroll
            for (int i = 0; i < 4; ++i)
                #pragma unroll
                for (int j = 0; j < 4; ++j) acc2[i][j] = add2(acc2[i][j], tacc2[i][j]);
        }
        __syncthreads();
    }
    #pragma unroll
    for (int i = 0; i < 4; ++i){
        float lo[4], hi[4];
        #pragma unroll
        for (int j = 0; j < 4; ++j) unpack2(lo[j], hi[j], acc2[i][j]);
        int row = m0 + (ry<<3) + 2*i;
        float4 c0 = {lo[0], lo[1], lo[2], lo[3]};
        float4 c1 = {hi[0], hi[1], hi[2], hi[3]};
        *(float4*)&Cmat[(size_t)row*N + n0 + (rx<<2)]       = c0;
        *(float4*)&Cmat[(size_t)(row+1)*N + n0 + (rx<<2)]   = c1;
    }
}

extern "C" __global__ void __launch_bounds__(256, 2)
k_qkv(const float* __restrict__ x, const float* __restrict__ Wq,
      const float* __restrict__ Wk, const float* __restrict__ Wv)
{
    const float* W = (blockIdx.z == 0) ? Wq : (blockIdx.z == 1) ? Wk : Wv;
    sgemm_tile(x, W, g_y[blockIdx.z], Cc, Cc, blockIdx.y, blockIdx.x);
}

// ---------------- 2-term bf16 split (output projection operands only) ----------------
extern "C" __global__ void __launch_bounds__(256)
k_split2(const float* __restrict__ src, int which, int n)
{
    int i = blockIdx.x * 256 + threadIdx.x;
    if (i * 4 >= n) return;
    const float* s = which ? src : (const float*)g_att;
    __nv_bfloat16* d1 = which ? g_w2[0] : g_a2[0];
    __nv_bfloat16* d2 = which ? g_w2[1] : g_a2[1];

    float4 v = *(const float4*)(s + (size_t)i*4);
    float x4[4] = {v.x, v.y, v.z, v.w};
    unsigned short u1[4], u2[4];
    #pragma unroll
    for (int j = 0; j < 4; ++j){
        float x = x4[j];
        __nv_bfloat16 b1 = __float2bfloat16_rn(x);
        float r = x - __bfloat162float(b1);
        __nv_bfloat16 b2 = __float2bfloat16_rn(r);
        u1[j] = *(unsigned short*)&b1;
        u2[j] = *(unsigned short*)&b2;
    }
    *(uint2*)((char*)d1 + (size_t)i*8) = make_uint2(u1[0] | ((unsigned)u1[1]<<16), u1[2] | ((unsigned)u1[3]<<16));
    *(uint2*)((char*)d2 + (size_t)i*8) = make_uint2(u2[0] | ((unsigned)u2[1]<<16), u2[2] | ((unsigned)u2[3]<<16));
}

// ------ emulated-fp32 OUT GEMM via mma.sync bf16 (CTA 128x64, K=1024, 2-term) ------
extern "C" __global__ void __launch_bounds__(256)
k_mma_out(float* __restrict__ out)
{
    __shared__ __align__(16) __nv_bfloat16 sm[2][4][128][16];   // 32KB
    const int tid = threadIdx.x, wid = tid >> 5, lane = tid & 31;
    const int warpM = wid & 3, warpN = wid >> 2;
    const int m0 = blockIdx.y * 128, n0 = blockIdx.x * 64;
    const __nv_bfloat16* segA[2] = {g_a2[0], g_a2[1]};
    const __nv_bfloat16* segB[2] = {g_w2[0], g_w2[1]};
    const int srow = tid >> 1, shalf = (tid & 1) << 3;
    const unsigned smbase = (unsigned)__cvta_generic_to_shared(&sm[0][0][0][0]);

    float accH[2][4][4], accL[2][4][4];
    #pragma unroll
    for (int mt = 0; mt < 2; ++mt)
        #pragma unroll
        for (int nf = 0; nf < 4; ++nf)
            #pragma unroll
            for (int r = 0; r < 4; ++r){ accH[mt][nf][r] = 0.f; accL[mt][nf][r] = 0.f; }

    #pragma unroll
    for (int s = 0; s < 2; ++s)
        cpa16(smbase + (unsigned)(((s*128 + srow)*16 + shalf)*2),
              segA[s] + (size_t)(m0 + srow)*Cc + shalf);
    if (tid < 128){
        #pragma unroll
        for (int s = 0; s < 2; ++s)
            cpa16(smbase + (unsigned)((((2+s)*128 + srow)*16 + shalf)*2),
                  segB[s] + (size_t)(n0 + srow)*Cc + shalf);
    }
    cpa_commit();

    for (int ch = 0; ch < 64; ++ch){
        const int buf = ch & 1;
        if (ch < 63){
            const unsigned bofs = (unsigned)((buf^1)*4*128*16*2);
            #pragma unroll
            for (int s = 0; s < 2; ++s)
                cpa16(smbase + bofs + (unsigned)(((s*128 + srow)*16 + shalf)*2),
                      segA[s] + (size_t)(m0 + srow)*Cc + (ch+1)*16 + shalf);
            if (tid < 128){
                #pragma unroll
                for (int s = 0; s < 2; ++s)
                    cpa16(smbase + bofs + (unsigned)((((2+s)*128 + srow)*16 + shalf)*2),
                          segB[s] + (size_t)(n0 + srow)*Cc + (ch+1)*16 + shalf);
            }
            cpa_commit();
            cpa_wait<1>();
        } else {
            cpa_wait<0>();
        }
        __syncthreads();

        unsigned af[2][2][4];
        #pragma unroll
        for (int s = 0; s < 2; ++s)
            #pragma unroll
            for (int mt = 0; mt < 2; ++mt){
                int row = warpM*32 + mt*16 + (lane & 15);
                unsigned ad = smbase + (unsigned)((((buf*4 + s)*128 + row)*16 + ((lane>>4)<<3))*2);
                ldsm4(af[s][mt][0], af[s][mt][1], af[s][mt][2], af[s][mt][3], ad);
            }
        #pragma unroll
        for (int n2 = 0; n2 < 2; ++n2){
            unsigned bfr[2][4];
            #pragma unroll
            for (int s = 0; s < 2; ++s){
                int row = warpN*32 + n2*16 + ((lane>>4)<<3) + (lane & 7);
                unsigned bd = smbase + (unsigned)((((buf*4 + 2 + s)*128 + row)*16 + (((lane>>3)&1)<<3))*2);
                ldsm4(bfr[s][0], bfr[s][1], bfr[s][2], bfr[s][3], bd);
            }
            #pragma unroll
            for (int mt = 0; mt < 2; ++mt)
                #pragma unroll
                for (int nt = 0; nt < 2; ++nt){
                    mma16816(accH[mt][n2*2+nt], af[0][mt], &bfr[0][nt*2]);
                    mma16816(accL[mt][n2*2+nt], af[0][mt], &bfr[1][nt*2]);
                    mma16816(accL[mt][n2*2+nt], af[1][mt], &bfr[0][nt*2]);
                }
        }
        __syncthreads();
    }

    const int g = lane >> 2, t4 = lane & 3;
    #pragma unroll
    for (int mt = 0; mt < 2; ++mt){
        int r0 = m0 + warpM*32 + mt*16 + g;
        #pragma unroll
        for (int nf = 0; nf < 4; ++nf){
            int col = n0 + warpN*32 + nf*8 + 2*t4;
            *(float2*)&out[(size_t)r0*Cc + col]     = make_float2(accH[mt][nf][0] + accL[mt][nf][0],
                                                                 accH[mt][nf][1] + accL[mt][nf][1]);
            *(float2*)&out[(size_t)(r0+8)*Cc + col] = make_float2(accH[mt][nf][2] + accL[mt][nf][2],
                                                                 accH[mt][nf][3] + accL[mt][nf][3]);
        }
    }
}

// ---------------- feature-dim top-8 sparsify (+ layout transforms) ----------------
extern "C" __global__ void __launch_bounds__(256)
k_sparsify()
{
    const int z   = blockIdx.y;                    // 0=q, 1=k, 2=v
    const int idx = blockIdx.x * 256 + threadIdx.x; // over B*T*H = 65536
    const int t = idx & (Tt - 1);
    const int h = (idx >> 11) & (Hh - 1);
    const int b = idx >> 15;

    const float* src = g_y[z] + ((size_t)(b*Tt + t))*Cc + h*Dd;
    float v[64];
    #pragma unroll
    for (int i = 0; i < 16; ++i){
        float4 f = *(const float4*)(src + i*4);
        v[4*i] = f.x; v[4*i+1] = f.y; v[4*i+2] = f.z; v[4*i+3] = f.w;
    }
    float thr[8];
    #pragma unroll
    for (int i = 0; i < 8; ++i) thr[i] = -1.f;
    #pragma unroll
    for (int d2 = 0; d2 < 64; ++d2){
        float a = fabsf(v[d2]);
        if (a > thr[0]){
            thr[0] = a;
            #pragma unroll
            for (int p = 0; p < 7; ++p){
                if (thr[p] > thr[p+1]){ float tmp = thr[p]; thr[p] = thr[p+1]; thr[p+1] = tmp; }
            }
        }
    }
    const float kth = thr[0];
    const size_t bh = (size_t)b*Hh + h;
    if (z == 1){
        #pragma unroll
        for (int d2 = 0; d2 < 64; ++d2){
            float val = (fabsf(v[d2]) >= kth) ? v[d2] : 0.f;
            g_kT[(bh*Dd + d2)*Tt + t] = val;     // coalesced over t within warp
        }
    } else {
        float* dst = ((z == 0) ? g_q : g_v) + (bh*Tt + t)*Dd;
        #pragma unroll
        for (int i = 0; i < 16; ++i){
            float4 o;
            o.x = (fabsf(v[4*i  ]) >= kth) ? v[4*i  ] : 0.f;
            o.y = (fabsf(v[4*i+1]) >= kth) ? v[4*i+1] : 0.f;
            o.z = (fabsf(v[4*i+2]) >= kth) ? v[4*i+2] : 0.f;
            o.w = (fabsf(v[4*i+3]) >= kth) ? v[4*i+3] : 0.f;
            *(float4*)(dst + 4*i) = o;
        }
    }
}

// ---- radix-select: find bin of rank-th largest. Warp-shuffle suffix scan, 2 barriers ----
__device__ __forceinline__ void radix_find(const unsigned* hist, int* scr,
                                           int rank, int tid, int* s_io)
{
    const int lane = tid & 31, wrp = tid >> 5;
    int sum = 0;
    #pragma unroll
    for (int i = 0; i < 8; ++i) sum += (int)hist[(tid<<3) + i];
    int v = sum;
    #pragma unroll
    for (int off = 1; off < 32; off <<= 1){
        int o = __shfl_down_sync(0xFFFFFFFFu, v, off);
        if (lane + off < 32) v += o;
    }
    if (lane == 0) scr[wrp] = v;    // warp total
    __syncthreads();
    int wsuf = 0;
    #pragma unroll
    for (int w = 0; w < 8; ++w) if (w > wrp) wsuf += scr[w];
    const int suff = v + wsuf;
    const int suffNext = suff - sum;
    if (suff >= rank && suffNext < rank){   // exactly one thread
        int c = suffNext;
        int bin = tid << 3;
        for (int i = (tid<<3) + 7; i >= (tid<<3); --i){
            if (c + (int)hist[i] >= rank){ bin = i; break; }
            c += (int)hist[i];
        }
        s_io[0] = bin; s_io[1] = rank - c;
    }
    __syncthreads();
}

// ---------------- fused sparse attention: one block per (b,h,t) query row ----------------
extern "C" __global__ void __launch_bounds__(256)
k_attn()
{
    __shared__ __align__(16) float s_scores[2048];   // scores; later AV reduction scratch
    __shared__ __align__(16) unsigned s_hist[2048];
    __shared__ __align__(16) unsigned short s_sel[2048];
    __shared__ float s_red[256];
    __shared__ float s_wred[8];
    __shared__ float s_qval[64];
    __shared__ int   s_qoff[64];     // premultiplied q-feature offsets (d * Tt)
    __shared__ int   s_wcnt[8];
    __shared__ int   s_io[2];
    __shared__ int   s_nq;

    const int tid = threadIdx.x;
    const int lane = tid & 31, wrp = tid >> 5;
    const int t = Tt - 1 - (int)blockIdx.x;   // heavy rows first
    const int h = blockIdx.y, b = blockIdx.z;
    const int len = t + 1;
    const size_t bh = (size_t)b*Hh + h;
    const bool selAll = (len <= 256);

    // ---- clear hist (only needed when radix select will run) + load q row ----
    if (!selAll){
        #pragma unroll
        for (int i = 0; i < 8; ++i) s_hist[tid + (i<<8)] = 0;
    }
    if (tid < 64) s_red[tid] = g_q[(bh*Tt + t)*Dd + tid];
    __syncthreads();
    if (tid == 0){
        int n = 0;
        for (int d = 0; d < 64; ++d){
            float qv = s_red[d];
            if (qv != 0.f){ s_qoff[n] = d * Tt; s_qval[n] = qv; ++n; }
        }
        s_nq = n;
    }
    __syncthreads();
    const int nq = s_nq;

    // ---- scores (sparse-q AXPY, ascending d) fused with pass-0 hist + row max ----
    const float* __restrict__ kT = g_kT + bh*Dd*Tt;
    float mloc = -__int_as_float(0x7F800000);   // -inf
    for (int s0 = tid*4; s0 < len; s0 += 1024){
        float ax=0.f, ay=0.f, az=0.f, aw=0.f;
        #pragma unroll 8
        for (int j = 0; j < nq; ++j){
            float qv = s_qval[j];
            float4 kv = *(const float4*)(kT + s_qoff[j] + s0);
            ax = fmaf(qv, kv.x, ax); ay = fmaf(qv, kv.y, ay);
            az = fmaf(qv, kv.z, az); aw = fmaf(qv, kv.w, aw);
        }
        float4 r = {ax*0.125f, ay*0.125f, az*0.125f, aw*0.125f};
        *(float4*)(s_scores + s0) = r;
        const int rem = len - s0;   // >= 1
        if (rem >= 4){
            mloc = fmaxf(fmaxf(fmaxf(fmaxf(mloc, r.x), r.y), r.z), r.w);
            if (!selAll){
                hadd(s_hist, okey(r.x) >> 21);
                hadd(s_hist, okey(r.y) >> 21);
                hadd(s_hist, okey(r.z) >> 21);
                hadd(s_hist, okey(r.w) >> 21);
            }
        } else {
            float vv[4] = {r.x, r.y, r.z, r.w};
            for (int e = 0; e < rem; ++e){
                mloc = fmaxf(mloc, vv[e]);
                if (!selAll) atomicAdd(&s_hist[okey(vv[e]) >> 21], 1u);
            }
        }
    }
    #pragma unroll
    for (int off = 16; off; off >>= 1)
        mloc = fmaxf(mloc, __shfl_xor_sync(0xFFFFFFFFu, mloc, off));
    if (lane == 0) s_wred[wrp] = mloc;
    __syncthreads();
    float m = s_wred[0];
    #pragma unroll
    for (int w = 1; w < 8; ++w) m = fmaxf(m, s_wred[w]);

    // ---- exact 256th-largest threshold via 3-pass radix select (float4 scans) ----
    unsigned thresh_u = 0;
    if (!selAll){
        int rank = 256;
        radix_find(s_hist, (int*)s_red, rank, tid, s_io);
        const unsigned b0 = (unsigned)s_io[0]; rank = s_io[1];
        __syncthreads();
        #pragma unroll
        for (int i = 0; i < 8; ++i) s_hist[tid + (i<<8)] = 0;
        __syncthreads();
        for (int s4 = tid*4; s4 < len; s4 += 1024){
            float4 sc = *(const float4*)(s_scores + s4);
            const int rem = len - s4;
            unsigned u;
            u = okey(sc.x); if ((u >> 21) == b0) atomicAdd(&s_hist[(u >> 10) & 0x7FFu], 1u);
            if (rem > 1){ u = okey(sc.y); if ((u >> 21) == b0) atomicAdd(&s_hist[(u >> 10) & 0x7FFu], 1u); }
            if (rem > 2){ u = okey(sc.z); if ((u >> 21) == b0) atomicAdd(&s_hist[(u >> 10) & 0x7FFu], 1u); }
            if (rem > 3){ u = okey(sc.w); if ((u >> 21) == b0) atomicAdd(&s_hist[(u >> 10) & 0x7FFu], 1u); }
        }
        __syncthreads();
        radix_find(s_hist, (int*)s_red, rank, tid, s_io);
        const unsigned b1 = (unsigned)s_io[0]; rank = s_io[1];
        __syncthreads();
        #pragma unroll
        for (int i = 0; i < 8; ++i) s_hist[tid + (i<<8)] = 0;
        __syncthreads();
        const unsigned hi21 = (b0 << 11) | b1;
        for (int s4 = tid*4; s4 < len; s4 += 1024){
            float4 sc = *(const float4*)(s_scores + s4);
            const int rem = len - s4;
            unsigned u;
            u = okey(sc.x); if ((u >> 10) == hi21) atomicAdd(&s_hist[u & 0x3FFu], 1u);
            if (rem > 1){ u = okey(sc.y); if ((u >> 10) == hi21) atomicAdd(&s_hist[u & 0x3FFu], 1u); }
            if (rem > 2){ u = okey(sc.z); if ((u >> 10) == hi21) atomicAdd(&s_hist[u & 0x3FFu], 1u); }
            if (rem > 3){ u = okey(sc.w); if ((u >> 10) == hi21) atomicAdd(&s_hist[u & 0x3FFu], 1u); }
        }
        __syncthreads();
        radix_find(s_hist, (int*)s_red, rank, tid, s_io);
        const unsigned b2 = (unsigned)s_io[0];
        __syncthreads();
        thresh_u = (b0 << 21) | (b1 << 10) | b2;
    }

    // ---- ordered compaction FUSED with softmax-weight generation ----
    float* s_wf = (float*)s_hist;   // hist no longer needed
    float zp = 0.f;
    int base = 0;
    for (int c0 = 0; c0 < len; c0 += 1024){
        const int s4 = c0 + tid*4;
        unsigned pb = 0; int cnt = 0;
        float4 sc = make_float4(0.f, 0.f, 0.f, 0.f);
        if (s4 < len){
            sc = *(const float4*)(s_scores + s4);
            const int rem = len - s4;
            if (selAll || okey(sc.x) >= thresh_u){ pb |= 1u; ++cnt; }
            if (rem > 1 && (selAll || okey(sc.y) >= thresh_u)){ pb |= 2u; ++cnt; }
            if (rem > 2 && (selAll || okey(sc.z) >= thresh_u)){ pb |= 4u; ++cnt; }
            if (rem > 3 && (selAll || okey(sc.w) >= thresh_u)){ pb |= 8u; ++cnt; }
        }
        int incl = cnt;
        #pragma unroll
        for (int off = 1; off < 32; off <<= 1){
            int o = __shfl_up_sync(0xFFFFFFFFu, incl, off);
            if (lane >= off) incl += o;
        }
        if (lane == 31) s_wcnt[wrp] = incl;
        __syncthreads();
        int woff = base, tot = 0;
        #pragma unroll
        for (int w = 0; w < 8; ++w){ int cg = s_wcnt[w]; if (w < wrp) woff += cg; tot += cg; }
        int pos = woff + (incl - cnt);
        const float scv[4] = {sc.x, sc.y, sc.z, sc.w};
        #pragma unroll
        for (int e = 0; e < 4; ++e){
            if ((pb >> e) & 1u){
                float ev = __expf(scv[e] - m);
                s_sel[pos] = (unsigned short)(s4 + e);
                s_wf[pos]  = ev;
                zp += ev;
                ++pos;
            }
        }
        base += tot;
        __syncthreads();
    }
    const int nsel = base;

    // ---- Z reduction ----
    #pragma unroll
    for (int off = 16; off; off >>= 1)
        zp += __shfl_xor_sync(0xFFFFFFFFu, zp, off);
    if (lane == 0) s_wred[wrp] = zp;
    __syncthreads();
    float Z = 0.f;
    #pragma unroll
    for (int w = 0; w < 8; ++w) Z += s_wred[w];
    const float invZ = 1.0f / Z;

    // ---- out = (sum of e * v[s,:]) * invZ  --- float4 gather:
    // thread = (ig, dq): ig in [0,16) index-group, dq in [0,16) d-quad.
    // 4x fewer LDG warp-ops + 4x less address math than the scalar gather.
    // (s_scores region is dead now -> reuse as the 16-partial reduction buffer.)
    const float* __restrict__ vp = g_v + bh*Tt*Dd;
    const int dq = tid & 15, ig = tid >> 4;
    float4 a4 = make_float4(0.f, 0.f, 0.f, 0.f);
    for (int i = ig; i < nsel; i += 16){
        const float w = s_wf[i];
        const float4 v4 = *(const float4*)(vp + (size_t)s_sel[i]*Dd + (dq << 2));
        a4.x = fmaf(w, v4.x, a4.x); a4.y = fmaf(w, v4.y, a4.y);
        a4.z = fmaf(w, v4.z, a4.z); a4.w = fmaf(w, v4.w, a4.w);
    }
    __syncthreads();               // s_scores free for reuse
    float* rv = s_scores;          // [16][68] pitch-padded partials
    rv[ig*68 + (dq<<2) + 0] = a4.x;
    rv[ig*68 + (dq<<2) + 1] = a4.y;
    rv[ig*68 + (dq<<2) + 2] = a4.z;
    rv[ig*68 + (dq<<2) + 3] = a4.w;
    __syncthreads();
    if (tid < 64){
        float r = 0.f;
        #pragma unroll
        for (int g2 = 0; g2 < 16; ++g2) r += rv[g2*68 + tid];
        g_att[(((size_t)b*Tt + t)*Hh + h)*Dd + tid] = r * invZ;
    }
}

// ---------------- launch ----------------
extern "C" void kernel_launch(void* const* d_in, const int* in_sizes, int n_in,
                              void* d_out, int out_size)
{
    (void)in_sizes; (void)n_in; (void)out_size;
    const float* x  = (const float*)d_in[0];
    const float* Wq = (const float*)d_in[1];
    const float* Wk = (const float*)d_in[2];
    const float* Wv = (const float*)d_in[3];
    const float* Wo = (const float*)d_in[4];
    float* out = (float*)d_out;

    const int nx = MM * Cc;      // 4M
    const int nw = Cc * Cc;      // 1M
    k_split2<<<nw/1024, 256>>>(Wo, 1, nw);           // Wo splits
    k_qkv<<<dim3(Cc/64, MM/128, 3), 256>>>(x, Wq, Wk, Wv);
    k_sparsify<<<dim3((Bb*Tt*Hh)/256, 3), 256>>>();
    k_attn<<<dim3(Tt, Hh, Bb), 256>>>();
    k_split2<<<nx/1024, 256>>>(x, 0, nx);            // g_att splits (src arg unused)
    k_mma_out<<<dim3(Cc/64, MM/128), 256>>>(out);
}